// round 3
// baseline (speedup 1.0000x reference)
#include <cuda_runtime.h>

// Uniform cubic B-spline evaluation via per-interval monomial (Horner) form.
// grid = linspace(-1,1,64) extended by 3 (h = 2/63), 63 intervals.
// For x in [-1,1): t = (x+1)*31.5, j = trunc(t), u = t-j,
//   out = p0[j] + u*(p1[j] + u*(p2[j] + u*p3[j]))
// where (p0..p3) = uniform-B-spline matrix applied to coeffs[j..j+3]:
//   p0 = (c0 + 4c1 + c2)/6
//   p1 = (c2 - c0)/2
//   p2 = (c0 - 2c1 + c2)/2
//   p3 = (-c0 + 3c1 - 3c2 + c3)/6
// Table replicated 8x across the eight 16B shared bank groups so every
// LDS.128 quarter-warp phase is conflict-free for random j.

#define REP 8
#define NTBL 63

__device__ __forceinline__ float eval_one(float x, const float4* __restrict__ tp) {
    float t = fmaf(x, 31.5f, 31.5f);
    int j = (int)t;                 // t >= 0, truncation == floor
    j = min(j, 62);
    float u = t - (float)j;
    float4 p = tp[j * REP];         // tp already offset by rep
    return fmaf(fmaf(fmaf(p.w, u, p.z), u, p.y), u, p.x);
}

__global__ void __launch_bounds__(256)
bspline_kernel(const float4* __restrict__ x4,
               const float* __restrict__ coeffs,
               float4* __restrict__ o4, int n4) {
    __shared__ float  csh[72];
    __shared__ float4 tbl[NTBL * REP];
    int tid = threadIdx.x;
    if (tid < 72) csh[tid] = (tid < 69) ? coeffs[tid] : 0.0f;
    __syncthreads();
    #pragma unroll
    for (int e = tid; e < NTBL * REP; e += 256) {
        int j = e >> 3;
        float c0 = csh[j], c1 = csh[j + 1], c2 = csh[j + 2], c3 = csh[j + 3];
        float4 p;
        p.x = (c0 + 4.0f * c1 + c2) * 0.16666666666666666f;
        p.y = (c2 - c0) * 0.5f;
        p.z = (c0 - 2.0f * c1 + c2) * 0.5f;
        p.w = (c3 - c0 + 3.0f * (c1 - c2)) * 0.16666666666666666f;
        tbl[e] = p;
    }
    __syncthreads();

    const float4* __restrict__ tp = tbl + (tid & (REP - 1));
    const int stride = gridDim.x * blockDim.x;

    // MLP=2: two independent float4 loads in flight per iteration.
    for (int i = blockIdx.x * blockDim.x + tid; i < n4; i += 2 * stride) {
        float4 xa = x4[i];
        int i2 = i + stride;
        bool has2 = (i2 < n4);
        float4 xb = has2 ? x4[i2] : make_float4(0.f, 0.f, 0.f, 0.f);

        float4 oa;
        oa.x = eval_one(xa.x, tp);
        oa.y = eval_one(xa.y, tp);
        oa.z = eval_one(xa.z, tp);
        oa.w = eval_one(xa.w, tp);
        o4[i] = oa;

        if (has2) {
            float4 ob;
            ob.x = eval_one(xb.x, tp);
            ob.y = eval_one(xb.y, tp);
            ob.z = eval_one(xb.z, tp);
            ob.w = eval_one(xb.w, tp);
            o4[i2] = ob;
        }
    }
}

extern "C" void kernel_launch(void* const* d_in, const int* in_sizes, int n_in,
                              void* d_out, int out_size) {
    const float* x      = (const float*)d_in[0];
    const float* coeffs = (const float*)d_in[1];
    float* out = (float*)d_out;
    int n  = in_sizes[0];
    int n4 = n >> 2;                 // N = 2^22, divisible by 4
    int threads = 256;
    int blocks  = 2048;              // ~14 CTAs/SM resident, deep latency hiding
    int max_blocks = (n4 + threads - 1) / threads;
    if (blocks > max_blocks) blocks = max_blocks;
    if (blocks < 1) blocks = 1;
    bspline_kernel<<<blocks, threads>>>((const float4*)x, coeffs, (float4*)out, n4);
}

// round 4
// speedup vs baseline: 1.4750x; 1.4750x over previous
#include <cuda_runtime.h>

// Uniform cubic B-spline via per-interval monomial (Horner) form.
// t = (x+1)*31.5, j = trunc(t) (clamped to 62), u = t-j,
// out = p0[j] + u*(p1[j] + u*(p2[j] + u*p3[j])), where
//   p0=(c0+4c1+c2)/6, p1=(c2-c0)/2, p2=(c0-2c1+c2)/2, p3=(c3-c0+3(c1-c2))/6.
// Table replicated 8x across the eight 16B shared bank groups ->
// every LDS.128 quarter-warp phase is conflict-free for random j.

#define REP 8
#define NTBL 63

__device__ __forceinline__ float eval_one(float x, const float4* __restrict__ tp) {
    float t = fmaf(x, 31.5f, 31.5f);
    int j = (int)t;                  // t >= 0: truncation == floor
    j = min(j, 62);                  // guard x -> t rounding up to 63.0
    float u = t - (float)j;
    float4 p = tp[j * REP];          // tp pre-offset by lane's bank-group
    return fmaf(fmaf(fmaf(p.w, u, p.z), u, p.y), u, p.x);
}

__device__ __forceinline__ float4 eval_four(float4 xv, const float4* __restrict__ tp) {
    float4 ov;
    ov.x = eval_one(xv.x, tp);
    ov.y = eval_one(xv.y, tp);
    ov.z = eval_one(xv.z, tp);
    ov.w = eval_one(xv.w, tp);
    return ov;
}

__global__ void __launch_bounds__(256)
bspline_kernel(const float4* __restrict__ x4,
               const float* __restrict__ coeffs,
               float4* __restrict__ o4, int n4) {
    __shared__ float4 tbl[NTBL * REP];
    int tid = threadIdx.x;
    #pragma unroll
    for (int e = tid; e < NTBL * REP; e += 256) {
        int j = e >> 3;
        float c0 = __ldg(coeffs + j);
        float c1 = __ldg(coeffs + j + 1);
        float c2 = __ldg(coeffs + j + 2);
        float c3 = __ldg(coeffs + j + 3);
        float4 p;
        p.x = fmaf(4.0f, c1, c0 + c2) * 0.16666666666666666f;
        p.y = (c2 - c0) * 0.5f;
        p.z = fmaf(-2.0f, c1, c0 + c2) * 0.5f;
        p.w = fmaf(3.0f, c1 - c2, c3 - c0) * 0.16666666666666666f;
        tbl[e] = p;
    }
    __syncthreads();

    const float4* __restrict__ tp = tbl + (tid & (REP - 1));
    const int stride = gridDim.x * blockDim.x;
    int i = blockIdx.x * blockDim.x + tid;

    // MLP=4 main loop: four independent float4 loads in flight.
    for (; i + 3 * stride < n4; i += 4 * stride) {
        float4 xa = x4[i];
        float4 xb = x4[i + stride];
        float4 xc = x4[i + 2 * stride];
        float4 xd = x4[i + 3 * stride];
        o4[i]              = eval_four(xa, tp);
        o4[i + stride]     = eval_four(xb, tp);
        o4[i + 2 * stride] = eval_four(xc, tp);
        o4[i + 3 * stride] = eval_four(xd, tp);
    }
    // MLP=2 tail
    if (i + stride < n4) {
        float4 xa = x4[i];
        float4 xb = x4[i + stride];
        o4[i]          = eval_four(xa, tp);
        o4[i + stride] = eval_four(xb, tp);
        i += 2 * stride;
    }
    // scalar tail
    if (i < n4) {
        float4 xa = x4[i];
        o4[i] = eval_four(xa, tp);
    }
}

extern "C" void kernel_launch(void* const* d_in, const int* in_sizes, int n_in,
                              void* d_out, int out_size) {
    const float* x      = (const float*)d_in[0];
    const float* coeffs = (const float*)d_in[1];
    float* out = (float*)d_out;
    int n  = in_sizes[0];
    int n4 = n >> 2;                 // N = 2^22, divisible by 4
    int threads = 256;
    int blocks  = 592;               // 4 CTAs/SM exactly, balanced wave
    int max_blocks = (n4 + threads - 1) / threads;
    if (blocks > max_blocks) blocks = max_blocks;
    if (blocks < 1) blocks = 1;
    bspline_kernel<<<blocks, threads>>>((const float4*)x, coeffs, (float4*)out, n4);
}